// round 2
// baseline (speedup 1.0000x reference)
#include <cuda_runtime.h>
#include <math.h>

#define SEQ 4096
#define HID 1024
#define FH  4096   // 4*HID

// Scratch (no cudaMalloc allowed): 64 MB xg buffer + h double buffer + barrier ctr
__device__ float g_xg[(size_t)SEQ * FH];
__device__ float g_hbuf[2][HID];
__device__ unsigned long long g_ctr;

// ---------------------------------------------------------------------------
// Kernel A: xg[s][r] = dot(emb[tok[s]], W_ih[r]) + b_ih[r] + b_hh[r]
// 128x128 tile, K-chunk 8, 256 threads, 8x8 microtile (strided 16 fragments).
// ---------------------------------------------------------------------------
__global__ __launch_bounds__(256) void xg_gemm(
    const int* __restrict__ tok, const float* __restrict__ emb,
    const float* __restrict__ Wih, const float* __restrict__ bih,
    const float* __restrict__ bhh)
{
    __shared__ float As[8][128];
    __shared__ float Bs[8][128];
    __shared__ int toks[128];

    const int tid = threadIdx.x;
    const int tx = tid & 15, ty = tid >> 4;
    const int s0 = blockIdx.y * 128;
    const int r0 = blockIdx.x * 128;

    if (tid < 128) toks[tid] = tok[s0 + tid];
    __syncthreads();

    float acc[8][8];
#pragma unroll
    for (int i = 0; i < 8; i++)
#pragma unroll
        for (int jj = 0; jj < 8; jj++) acc[i][jj] = 0.f;

    const int lrow = tid >> 1;
    const int kq = (tid & 1) * 4;

    for (int k0 = 0; k0 < HID; k0 += 8) {
        float4 av = *(const float4*)(emb + (size_t)toks[lrow] * HID + k0 + kq);
        float4 bv = *(const float4*)(Wih + (size_t)(r0 + lrow) * HID + k0 + kq);
        As[kq + 0][lrow] = av.x; As[kq + 1][lrow] = av.y;
        As[kq + 2][lrow] = av.z; As[kq + 3][lrow] = av.w;
        Bs[kq + 0][lrow] = bv.x; Bs[kq + 1][lrow] = bv.y;
        Bs[kq + 2][lrow] = bv.z; Bs[kq + 3][lrow] = bv.w;
        __syncthreads();
#pragma unroll
        for (int kk = 0; kk < 8; kk++) {
            float a[8], b[8];
#pragma unroll
            for (int i = 0; i < 8; i++) a[i] = As[kk][ty + 16 * i];
#pragma unroll
            for (int jj = 0; jj < 8; jj++) b[jj] = Bs[kk][tx + 16 * jj];
#pragma unroll
            for (int i = 0; i < 8; i++)
#pragma unroll
                for (int jj = 0; jj < 8; jj++)
                    acc[i][jj] = fmaf(a[i], b[jj], acc[i][jj]);
        }
        __syncthreads();
    }

    float bias[8];
#pragma unroll
    for (int jj = 0; jj < 8; jj++) {
        int r = r0 + tx + 16 * jj;
        bias[jj] = bih[r] + bhh[r];
    }
#pragma unroll
    for (int i = 0; i < 8; i++) {
        int s = s0 + ty + 16 * i;
#pragma unroll
        for (int jj = 0; jj < 8; jj++)
            g_xg[(size_t)s * FH + r0 + tx + 16 * jj] = acc[i][jj] + bias[jj];
    }
}

// ---------------------------------------------------------------------------
// Kernel B: persistent 128-CTA LSTM scan. W_hh lives in registers.
// Block b owns h-units j = b*8 .. b*8+7.  For unit g: 64 threads (2 warps)
// cover K=1024 (16 contiguous k each), each holding the 4 gate rows' weights.
// Grid barrier = monotonic release-atomic counter + acquire spin.
// ---------------------------------------------------------------------------
__device__ __forceinline__ unsigned long long ld_acq(const unsigned long long* p)
{
    unsigned long long v;
    asm volatile("ld.acquire.gpu.global.u64 %0, [%1];" : "=l"(v) : "l"(p));
    return v;
}
__device__ __forceinline__ float sigf(float x) { return 1.f / (1.f + __expf(-x)); }

__global__ __launch_bounds__(512) void lstm_scan(
    const float* __restrict__ Whh, const float* __restrict__ h0,
    const float* __restrict__ c0)
{
    __shared__ float part[8][4][2];
    const int tid = threadIdx.x;
    const int g   = tid >> 6;        // h-unit within block (0..7)
    const int tau = tid & 63;        // k-slice index (0..63), 16 k each
    const int wig = tau >> 5;        // warp within group (0..1)
    const int j   = blockIdx.x * 8 + g;

    // Preload W_hh rows {i,f,g,o} for unit j, k in [tau*16, tau*16+16)
    float w[4][16];
#pragma unroll
    for (int gate = 0; gate < 4; gate++) {
        const float4* p =
            (const float4*)(Whh + ((size_t)(gate * HID + j)) * HID + tau * 16);
#pragma unroll
        for (int q = 0; q < 4; q++) {
            float4 v = __ldg(p + q);
            w[gate][q * 4 + 0] = v.x; w[gate][q * 4 + 1] = v.y;
            w[gate][q * 4 + 2] = v.z; w[gate][q * 4 + 3] = v.w;
        }
    }

    const bool des = (tau == 0);     // designated thread for unit g
    float cst = des ? __ldg(c0 + j) : 0.f;

    for (int t = 0; t < SEQ; t++) {
        // Prefetch xg[t] (independent of h) before the barrier spin
        float xr0 = 0.f, xr1 = 0.f, xr2 = 0.f, xr3 = 0.f;
        if (des) {
            const float* xp = g_xg + (size_t)t * FH + j;
            xr0 = __ldg(xp);
            xr1 = __ldg(xp + HID);
            xr2 = __ldg(xp + 2 * HID);
            xr3 = __ldg(xp + 3 * HID);
        }
        if (t > 0) {
            if (tid == 0) {
                const unsigned long long tgt = 128ull * (unsigned long long)t;
                while (ld_acq(&g_ctr) < tgt) { }
            }
            __syncthreads();
        }
        const float* hsrc = (t == 0) ? h0 : g_hbuf[(t - 1) & 1];

        float acc0 = 0.f, acc1 = 0.f, acc2 = 0.f, acc3 = 0.f;
        const float4* hp = (const float4*)(hsrc + tau * 16);
#pragma unroll
        for (int q = 0; q < 4; q++) {
            float4 hv = __ldcg(hp + q);   // .cg: bypass (incoherent) L1
            float hx[4] = {hv.x, hv.y, hv.z, hv.w};
#pragma unroll
            for (int e = 0; e < 4; e++) {
                acc0 = fmaf(w[0][q * 4 + e], hx[e], acc0);
                acc1 = fmaf(w[1][q * 4 + e], hx[e], acc1);
                acc2 = fmaf(w[2][q * 4 + e], hx[e], acc2);
                acc3 = fmaf(w[3][q * 4 + e], hx[e], acc3);
            }
        }
#pragma unroll
        for (int off = 16; off >= 1; off >>= 1) {
            acc0 += __shfl_xor_sync(0xffffffffu, acc0, off);
            acc1 += __shfl_xor_sync(0xffffffffu, acc1, off);
            acc2 += __shfl_xor_sync(0xffffffffu, acc2, off);
            acc3 += __shfl_xor_sync(0xffffffffu, acc3, off);
        }
        if ((tau & 31) == 0) {
            part[g][0][wig] = acc0;
            part[g][1][wig] = acc1;
            part[g][2][wig] = acc2;
            part[g][3][wig] = acc3;
        }
        __syncthreads();
        if (des) {
            float p0 = part[g][0][0] + part[g][0][1] + xr0;
            float p1 = part[g][1][0] + part[g][1][1] + xr1;
            float p2 = part[g][2][0] + part[g][2][1] + xr2;
            float p3 = part[g][3][0] + part[g][3][1] + xr3;
            float iv = sigf(p0), fv = sigf(p1);
            float gv = tanhf(p2), ov = sigf(p3);
            cst = fv * cst + iv * gv;
            g_hbuf[t & 1][j] = ov * tanhf(cst);
            __threadfence();            // make h visible at gpu scope
        }
        __syncthreads();
        if (tid == 0) {
            // release: pairs with ld.acquire spin in other blocks
            asm volatile("red.release.gpu.global.add.u64 [%0], %1;"
                         :: "l"(&g_ctr), "l"(1ull) : "memory");
        }
    }
}

// ---------------------------------------------------------------------------
// Kernel C: reset barrier counter (stream-ordered after the scan) so the
// captured graph is replayable deterministically.
// ---------------------------------------------------------------------------
__global__ void reset_ctr_k() { g_ctr = 0ull; }

// ---------------------------------------------------------------------------
// Kernel D: out = log_softmax(h_final)   (h_final = g_hbuf[(SEQ-1)&1])
// ---------------------------------------------------------------------------
__global__ __launch_bounds__(1024) void logsoftmax_k(float* __restrict__ out)
{
    __shared__ float red[32];
    __shared__ float s_m, s_s;
    const int tid = threadIdx.x;
    float x = g_hbuf[(SEQ - 1) & 1][tid];

    float m = x;
#pragma unroll
    for (int off = 16; off >= 1; off >>= 1)
        m = fmaxf(m, __shfl_xor_sync(0xffffffffu, m, off));
    if ((tid & 31) == 0) red[tid >> 5] = m;
    __syncthreads();
    if (tid < 32) {
        float v = red[tid];
#pragma unroll
        for (int off = 16; off >= 1; off >>= 1)
            v = fmaxf(v, __shfl_xor_sync(0xffffffffu, v, off));
        if (tid == 0) s_m = v;
    }
    __syncthreads();

    float e = __expf(x - s_m);
    float s = e;
#pragma unroll
    for (int off = 16; off >= 1; off >>= 1)
        s += __shfl_xor_sync(0xffffffffu, s, off);
    if ((tid & 31) == 0) red[tid >> 5] = s;
    __syncthreads();
    if (tid < 32) {
        float v = red[tid];
#pragma unroll
        for (int off = 16; off >= 1; off >>= 1)
            v += __shfl_xor_sync(0xffffffffu, v, off);
        if (tid == 0) s_s = v;
    }
    __syncthreads();

    out[tid] = x - s_m - logf(s_s);
}

// ---------------------------------------------------------------------------
extern "C" void kernel_launch(void* const* d_in, const int* in_sizes, int n_in,
                              void* d_out, int out_size)
{
    const int*   tok = (const int*)  d_in[0];
    const float* emb = (const float*)d_in[1];
    const float* Wih = (const float*)d_in[2];
    const float* Whh = (const float*)d_in[3];
    const float* bih = (const float*)d_in[4];
    const float* bhh = (const float*)d_in[5];
    const float* h0  = (const float*)d_in[6];
    const float* c0  = (const float*)d_in[7];
    float* out = (float*)d_out;

    xg_gemm<<<dim3(FH / 128, SEQ / 128), 256>>>(tok, emb, Wih, bih, bhh);
    lstm_scan<<<128, 512>>>(Whh, h0, c0);
    reset_ctr_k<<<1, 1>>>();
    logsoftmax_k<<<1, 1024>>>(out);
}

// round 3
// speedup vs baseline: 1.0314x; 1.0314x over previous
#include <cuda_runtime.h>
#include <math.h>

#define SEQ 4096
#define HID 1024
#define FH  4096   // 4*HID
#define NB  128    // scan blocks

// Scratch (no cudaMalloc allowed)
__device__ float g_xg[(size_t)SEQ * FH];
__device__ float g_hbuf[2][HID];
__device__ unsigned int g_flag[NB * 8];   // 32B-padded per-block step flags

// ---------------- packed f32x2 helpers (sm_103a) ----------------
__device__ __forceinline__ unsigned long long pk2(float x, float y) {
    unsigned long long r;
    asm("mov.b64 %0, {%1, %2};" : "=l"(r) : "f"(x), "f"(y));
    return r;
}
__device__ __forceinline__ void upk2(unsigned long long v, float& x, float& y) {
    asm("mov.b64 {%0, %1}, %2;" : "=f"(x), "=f"(y) : "l"(v));
}
__device__ __forceinline__ unsigned long long fma2(
    unsigned long long a, unsigned long long b, unsigned long long c) {
    unsigned long long d;
    asm("fma.rn.f32x2 %0, %1, %2, %3;" : "=l"(d) : "l"(a), "l"(b), "l"(c));
    return d;
}

__device__ __forceinline__ unsigned int ld_acq(const unsigned int* p) {
    unsigned int v;
    asm volatile("ld.acquire.gpu.global.u32 %0, [%1];" : "=r"(v) : "l"(p));
    return v;
}
__device__ __forceinline__ void st_rel(unsigned int* p, unsigned int v) {
    asm volatile("st.release.gpu.global.u32 [%0], %1;" :: "l"(p), "r"(v) : "memory");
}

// ---------------------------------------------------------------------------
// Kernel A: xg[s][r] = dot(emb[tok[s]], W_ih[r]) + b_ih[r] + b_hh[r]
// 128x128 tile, K-chunk 8, 256 threads, 8x8 microtile, f32x2 FMAs,
// double-buffered smem with register staging.
// ---------------------------------------------------------------------------
__global__ __launch_bounds__(256) void xg_gemm(
    const int* __restrict__ tok, const float* __restrict__ emb,
    const float* __restrict__ Wih, const float* __restrict__ bih,
    const float* __restrict__ bhh)
{
    __shared__ float As[2][8][128];
    __shared__ float Bs[2][8][128];
    __shared__ int toks[128];

    const int tid = threadIdx.x;
    const int tx = tid & 15, ty = tid >> 4;
    const int s0 = blockIdx.y * 128;
    const int r0 = blockIdx.x * 128;

    if (tid < 128) toks[tid] = tok[s0 + tid];
    __syncthreads();

    unsigned long long acc2[8][4];
#pragma unroll
    for (int i = 0; i < 8; i++)
#pragma unroll
        for (int jp = 0; jp < 4; jp++) acc2[i][jp] = pk2(0.f, 0.f);

    const int lrow = tid >> 1;
    const int kq = (tid & 1) * 4;
    const size_t arow = (size_t)toks[lrow] * HID + kq;
    const size_t brow = (size_t)(r0 + lrow) * HID + kq;

    float4 av = *(const float4*)(emb + arow);
    float4 bv = *(const float4*)(Wih + brow);

    int buf = 0;
    for (int k0 = 0; k0 < HID; k0 += 8) {
        As[buf][kq + 0][lrow] = av.x; As[buf][kq + 1][lrow] = av.y;
        As[buf][kq + 2][lrow] = av.z; As[buf][kq + 3][lrow] = av.w;
        Bs[buf][kq + 0][lrow] = bv.x; Bs[buf][kq + 1][lrow] = bv.y;
        Bs[buf][kq + 2][lrow] = bv.z; Bs[buf][kq + 3][lrow] = bv.w;
        __syncthreads();
        if (k0 + 8 < HID) {
            av = *(const float4*)(emb + arow + k0 + 8);
            bv = *(const float4*)(Wih + brow + k0 + 8);
        }
#pragma unroll
        for (int kk = 0; kk < 8; kk++) {
            float4 alo = *(const float4*)&As[buf][kk][ty * 4];
            float4 ahi = *(const float4*)&As[buf][kk][64 + ty * 4];
            float4 blo = *(const float4*)&Bs[buf][kk][tx * 4];
            float4 bhi = *(const float4*)&Bs[buf][kk][64 + tx * 4];
            unsigned long long b2[4] = {
                pk2(blo.x, blo.y), pk2(blo.z, blo.w),
                pk2(bhi.x, bhi.y), pk2(bhi.z, bhi.w)};
            float a[8] = {alo.x, alo.y, alo.z, alo.w,
                          ahi.x, ahi.y, ahi.z, ahi.w};
#pragma unroll
            for (int i = 0; i < 8; i++) {
                unsigned long long ad = pk2(a[i], a[i]);
#pragma unroll
                for (int jp = 0; jp < 4; jp++)
                    acc2[i][jp] = fma2(ad, b2[jp], acc2[i][jp]);
            }
        }
        buf ^= 1;
    }

    // bias (b_ih + b_hh) for the two 4-col groups
    float4 bl1 = *(const float4*)(bih + r0 + tx * 4);
    float4 bl2 = *(const float4*)(bhh + r0 + tx * 4);
    float4 bh1 = *(const float4*)(bih + r0 + 64 + tx * 4);
    float4 bh2 = *(const float4*)(bhh + r0 + 64 + tx * 4);
    float4 biasl = {bl1.x + bl2.x, bl1.y + bl2.y, bl1.z + bl2.z, bl1.w + bl2.w};
    float4 biash = {bh1.x + bh2.x, bh1.y + bh2.y, bh1.z + bh2.z, bh1.w + bh2.w};

#pragma unroll
    for (int i = 0; i < 8; i++) {
        int s = s0 + ((i < 4) ? (ty * 4 + i) : (64 + ty * 4 + i - 4));
        float4 o1, o2;
        upk2(acc2[i][0], o1.x, o1.y); upk2(acc2[i][1], o1.z, o1.w);
        upk2(acc2[i][2], o2.x, o2.y); upk2(acc2[i][3], o2.z, o2.w);
        o1.x += biasl.x; o1.y += biasl.y; o1.z += biasl.z; o1.w += biasl.w;
        o2.x += biash.x; o2.y += biash.y; o2.z += biash.z; o2.w += biash.w;
        *(float4*)(g_xg + (size_t)s * FH + r0 + tx * 4) = o1;
        *(float4*)(g_xg + (size_t)s * FH + r0 + 64 + tx * 4) = o2;
    }
}

// ---------------------------------------------------------------------------
// Kernel B: persistent 128-CTA LSTM scan. W_hh in registers (f32x2 packed).
// Sync: per-block release flag; 128 parallel acquire-pollers per block.
// ---------------------------------------------------------------------------
__global__ __launch_bounds__(512) void lstm_scan(
    const float* __restrict__ Whh, const float* __restrict__ h0,
    const float* __restrict__ c0)
{
    __shared__ float part[8][4][2];
    const int tid  = threadIdx.x;
    const int g    = tid >> 6;       // unit within block (0..7)
    const int tau  = tid & 63;       // k-slice (0..63), 16 k each
    const int wig  = tau >> 5;       // warp within group
    const int lane = tid & 31;
    const int j    = blockIdx.x * 8 + g;

    // Preload W_hh rows {i,f,g,o} for unit j, packed f32x2
    unsigned long long w2[4][8];
#pragma unroll
    for (int gate = 0; gate < 4; gate++) {
        const float4* p =
            (const float4*)(Whh + ((size_t)(gate * HID + j)) * HID + tau * 16);
#pragma unroll
        for (int q = 0; q < 4; q++) {
            float4 v = __ldg(p + q);
            w2[gate][2 * q + 0] = pk2(v.x, v.y);
            w2[gate][2 * q + 1] = pk2(v.z, v.w);
        }
    }

    float cst = (tau == 0) ? __ldg(c0 + j) : 0.f;
    const int gl = tau & 3;
    const float nl_scale = (gl == 2) ? 2.f : 1.f;   // tanh lane uses sig(2x)

    for (int t = 0; t < SEQ; t++) {
        // xg prefetch (independent of h): lanes tau<4 each fetch one gate's x
        float xr = 0.f;
        if (tau < 4)
            xr = __ldg(g_xg + (size_t)t * FH + tau * HID + j);

        if (t > 0) {
            if (tid < NB) {
                const unsigned int* f = &g_flag[tid * 8];
                while (ld_acq(f) < (unsigned int)t) { }
            }
            __syncthreads();
        }
        const float* hsrc = (t == 0) ? h0 : g_hbuf[(t - 1) & 1];

        unsigned long long a0 = pk2(0.f, 0.f), a1 = a0, a2 = a0, a3 = a0;
        const float4* hp = (const float4*)(hsrc + tau * 16);
#pragma unroll
        for (int q = 0; q < 4; q++) {
            float4 hv = __ldcg(hp + q);
            unsigned long long h01 = pk2(hv.x, hv.y);
            unsigned long long h23 = pk2(hv.z, hv.w);
            a0 = fma2(w2[0][2 * q], h01, a0); a0 = fma2(w2[0][2 * q + 1], h23, a0);
            a1 = fma2(w2[1][2 * q], h01, a1); a1 = fma2(w2[1][2 * q + 1], h23, a1);
            a2 = fma2(w2[2][2 * q], h01, a2); a2 = fma2(w2[2][2 * q + 1], h23, a2);
            a3 = fma2(w2[3][2 * q], h01, a3); a3 = fma2(w2[3][2 * q + 1], h23, a3);
        }
        float acc[4];
        { float x, y; upk2(a0, x, y); acc[0] = x + y;
          upk2(a1, x, y); acc[1] = x + y;
          upk2(a2, x, y); acc[2] = x + y;
          upk2(a3, x, y); acc[3] = x + y; }
#pragma unroll
        for (int off = 16; off >= 1; off >>= 1) {
            acc[0] += __shfl_xor_sync(0xffffffffu, acc[0], off);
            acc[1] += __shfl_xor_sync(0xffffffffu, acc[1], off);
            acc[2] += __shfl_xor_sync(0xffffffffu, acc[2], off);
            acc[3] += __shfl_xor_sync(0xffffffffu, acc[3], off);
        }
        if (lane == 0) {
            part[g][0][wig] = acc[0];
            part[g][1][wig] = acc[1];
            part[g][2][wig] = acc[2];
            part[g][3][wig] = acc[3];
        }
        __syncthreads();

        if (wig == 0) {
            // lanes 0..3 compute the four gate activations in parallel
            float p = part[g][gl][0] + part[g][gl][1] + xr;
            float s = 1.f / (1.f + __expf(-nl_scale * p));
            float act = (gl == 2) ? (2.f * s - 1.f) : s;
            float iv = __shfl_sync(0xffffffffu, act, 0);
            float fv = __shfl_sync(0xffffffffu, act, 1);
            float gv = __shfl_sync(0xffffffffu, act, 2);
            float ov = __shfl_sync(0xffffffffu, act, 3);
            if (tau == 0) {
                cst = fv * cst + iv * gv;
                float s2 = 1.f / (1.f + __expf(-2.f * cst));
                g_hbuf[t & 1][j] = ov * (2.f * s2 - 1.f);
            }
        }
        __syncthreads();   // orders h stores (cta) before the release below
        if (tid == 0)
            st_rel(&g_flag[blockIdx.x * 8], (unsigned int)(t + 1));
    }
}

// ---------------------------------------------------------------------------
// Kernel C: reset flags so the captured graph replays deterministically.
// ---------------------------------------------------------------------------
__global__ void reset_flags_k() {
    g_flag[threadIdx.x] = 0u;
}

// ---------------------------------------------------------------------------
// Kernel D: out = log_softmax(h_final)
// ---------------------------------------------------------------------------
__global__ __launch_bounds__(1024) void logsoftmax_k(float* __restrict__ out)
{
    __shared__ float red[32];
    __shared__ float s_m, s_s;
    const int tid = threadIdx.x;
    float x = g_hbuf[(SEQ - 1) & 1][tid];

    float m = x;
#pragma unroll
    for (int off = 16; off >= 1; off >>= 1)
        m = fmaxf(m, __shfl_xor_sync(0xffffffffu, m, off));
    if ((tid & 31) == 0) red[tid >> 5] = m;
    __syncthreads();
    if (tid < 32) {
        float v = red[tid];
#pragma unroll
        for (int off = 16; off >= 1; off >>= 1)
            v = fmaxf(v, __shfl_xor_sync(0xffffffffu, v, off));
        if (tid == 0) s_m = v;
    }
    __syncthreads();

    float e = __expf(x - s_m);
    float s = e;
#pragma unroll
    for (int off = 16; off >= 1; off >>= 1)
        s += __shfl_xor_sync(0xffffffffu, s, off);
    if ((tid & 31) == 0) red[tid >> 5] = s;
    __syncthreads();
    if (tid < 32) {
        float v = red[tid];
#pragma unroll
        for (int off = 16; off >= 1; off >>= 1)
            v += __shfl_xor_sync(0xffffffffu, v, off);
        if (tid == 0) s_s = v;
    }
    __syncthreads();

    out[tid] = x - s_m - logf(s_s);
}

// ---------------------------------------------------------------------------
extern "C" void kernel_launch(void* const* d_in, const int* in_sizes, int n_in,
                              void* d_out, int out_size)
{
    const int*   tok = (const int*)  d_in[0];
    const float* emb = (const float*)d_in[1];
    const float* Wih = (const float*)d_in[2];
    const float* Whh = (const float*)d_in[3];
    const float* bih = (const float*)d_in[4];
    const float* bhh = (const float*)d_in[5];
    const float* h0  = (const float*)d_in[6];
    const float* c0  = (const float*)d_in[7];
    float* out = (float*)d_out;

    xg_gemm<<<dim3(FH / 128, SEQ / 128), 256>>>(tok, emb, Wih, bih, bhh);
    lstm_scan<<<NB, 512>>>(Whh, h0, c0);
    reset_flags_k<<<1, NB * 8>>>();
    logsoftmax_k<<<1, 1024>>>(out);
}

// round 6
// speedup vs baseline: 2.5914x; 2.5126x over previous
#include <cuda_runtime.h>
#include <math.h>

#define SEQ 4096
#define HID 1024
#define FH  4096   // 4*HID
#define NB  128    // scan blocks

// Scratch (no cudaMalloc allowed)
__device__ float g_xg[(size_t)SEQ * FH];
__device__ float g_hbuf[2][HID];
__device__ unsigned int g_flag[NB * 8];   // 32B-padded per-block step flags

// ---------------- packed f32x2 helpers (sm_103a) ----------------
__device__ __forceinline__ unsigned long long pk2(float x, float y) {
    unsigned long long r;
    asm("mov.b64 %0, {%1, %2};" : "=l"(r) : "f"(x), "f"(y));
    return r;
}
__device__ __forceinline__ void upk2(unsigned long long v, float& x, float& y) {
    asm("mov.b64 {%0, %1}, %2;" : "=f"(x), "=f"(y) : "l"(v));
}
__device__ __forceinline__ unsigned long long fma2(
    unsigned long long a, unsigned long long b, unsigned long long c) {
    unsigned long long d;
    asm("fma.rn.f32x2 %0, %1, %2, %3;" : "=l"(d) : "l"(a), "l"(b), "l"(c));
    return d;
}

__device__ __forceinline__ unsigned int ld_acq(const unsigned int* p) {
    unsigned int v;
    asm volatile("ld.acquire.gpu.global.u32 %0, [%1];" : "=r"(v) : "l"(p));
    return v;
}
__device__ __forceinline__ void st_rel(unsigned int* p, unsigned int v) {
    asm volatile("st.release.gpu.global.u32 [%0], %1;" :: "l"(p), "r"(v) : "memory");
}

// ---------------------------------------------------------------------------
// Kernel A: xg[s][r] = dot(emb[tok[s]], W_ih[r]) + b_ih[r] + b_hh[r]
// (unchanged from R3 — bounded ≤ ~2 ms; revisit only if it shows up on top)
// ---------------------------------------------------------------------------
__global__ __launch_bounds__(256) void xg_gemm(
    const int* __restrict__ tok, const float* __restrict__ emb,
    const float* __restrict__ Wih, const float* __restrict__ bih,
    const float* __restrict__ bhh)
{
    __shared__ float As[2][8][128];
    __shared__ float Bs[2][8][128];
    __shared__ int toks[128];

    const int tid = threadIdx.x;
    const int tx = tid & 15, ty = tid >> 4;
    const int s0 = blockIdx.y * 128;
    const int r0 = blockIdx.x * 128;

    if (tid < 128) toks[tid] = tok[s0 + tid];
    __syncthreads();

    unsigned long long acc2[8][4];
#pragma unroll
    for (int i = 0; i < 8; i++)
#pragma unroll
        for (int jp = 0; jp < 4; jp++) acc2[i][jp] = pk2(0.f, 0.f);

    const int lrow = tid >> 1;
    const int kq = (tid & 1) * 4;
    const size_t arow = (size_t)toks[lrow] * HID + kq;
    const size_t brow = (size_t)(r0 + lrow) * HID + kq;

    float4 av = *(const float4*)(emb + arow);
    float4 bv = *(const float4*)(Wih + brow);

    int buf = 0;
    for (int k0 = 0; k0 < HID; k0 += 8) {
        As[buf][kq + 0][lrow] = av.x; As[buf][kq + 1][lrow] = av.y;
        As[buf][kq + 2][lrow] = av.z; As[buf][kq + 3][lrow] = av.w;
        Bs[buf][kq + 0][lrow] = bv.x; Bs[buf][kq + 1][lrow] = bv.y;
        Bs[buf][kq + 2][lrow] = bv.z; Bs[buf][kq + 3][lrow] = bv.w;
        __syncthreads();
        if (k0 + 8 < HID) {
            av = *(const float4*)(emb + arow + k0 + 8);
            bv = *(const float4*)(Wih + brow + k0 + 8);
        }
#pragma unroll
        for (int kk = 0; kk < 8; kk++) {
            float4 alo = *(const float4*)&As[buf][kk][ty * 4];
            float4 ahi = *(const float4*)&As[buf][kk][64 + ty * 4];
            float4 blo = *(const float4*)&Bs[buf][kk][tx * 4];
            float4 bhi = *(const float4*)&Bs[buf][kk][64 + tx * 4];
            unsigned long long b2[4] = {
                pk2(blo.x, blo.y), pk2(blo.z, blo.w),
                pk2(bhi.x, bhi.y), pk2(bhi.z, bhi.w)};
            float a[8] = {alo.x, alo.y, alo.z, alo.w,
                          ahi.x, ahi.y, ahi.z, ahi.w};
#pragma unroll
            for (int i = 0; i < 8; i++) {
                unsigned long long ad = pk2(a[i], a[i]);
#pragma unroll
                for (int jp = 0; jp < 4; jp++)
                    acc2[i][jp] = fma2(ad, b2[jp], acc2[i][jp]);
            }
        }
        buf ^= 1;
    }

    float4 bl1 = *(const float4*)(bih + r0 + tx * 4);
    float4 bl2 = *(const float4*)(bhh + r0 + tx * 4);
    float4 bh1 = *(const float4*)(bih + r0 + 64 + tx * 4);
    float4 bh2 = *(const float4*)(bhh + r0 + 64 + tx * 4);
    float4 biasl = {bl1.x + bl2.x, bl1.y + bl2.y, bl1.z + bl2.z, bl1.w + bl2.w};
    float4 biash = {bh1.x + bh2.x, bh1.y + bh2.y, bh1.z + bh2.z, bh1.w + bh2.w};

#pragma unroll
    for (int i = 0; i < 8; i++) {
        int s = s0 + ((i < 4) ? (ty * 4 + i) : (64 + ty * 4 + i - 4));
        float4 o1, o2;
        upk2(acc2[i][0], o1.x, o1.y); upk2(acc2[i][1], o1.z, o1.w);
        upk2(acc2[i][2], o2.x, o2.y); upk2(acc2[i][3], o2.z, o2.w);
        o1.x += biasl.x; o1.y += biasl.y; o1.z += biasl.z; o1.w += biasl.w;
        o2.x += biash.x; o2.y += biash.y; o2.z += biash.z; o2.w += biash.w;
        *(float4*)(g_xg + (size_t)s * FH + r0 + tx * 4) = o1;
        *(float4*)(g_xg + (size_t)s * FH + r0 + 64 + tx * 4) = o2;
    }
}

// ---------------------------------------------------------------------------
// Kernel B: persistent 128-CTA scan, 256 threads, ONE WARP PER UNIT.
// h is staged once per block through smem (coalesced 4KB) instead of each
// thread pulling its slice from L2 (kills the 4MB/step L2 fan-out burst).
// W_hh in registers: per thread 4 gates x 32 k = 128 floats (f32x2 packed).
// ---------------------------------------------------------------------------
__global__ __launch_bounds__(256, 1) void lstm_scan(
    const float* __restrict__ Whh, const float* __restrict__ h0,
    const float* __restrict__ c0)
{
    __shared__ float sh[32][33];     // h staged: h[k] at sh[k&31][k>>5]
    const int tid  = threadIdx.x;
    const int wid  = tid >> 5;       // unit within block (0..7)
    const int lane = tid & 31;
    const int j    = blockIdx.x * 8 + wid;

    // Preload W_hh rows {i,f,g,o} for unit j, k in [lane*32, lane*32+32)
    unsigned long long w2[4][16];
#pragma unroll
    for (int gate = 0; gate < 4; gate++) {
        const float4* p =
            (const float4*)(Whh + ((size_t)(gate * HID + j)) * HID + lane * 32);
#pragma unroll
        for (int q = 0; q < 8; q++) {
            float4 v = __ldg(p + q);
            w2[gate][2 * q + 0] = pk2(v.x, v.y);
            w2[gate][2 * q + 1] = pk2(v.z, v.w);
        }
    }

    float cst = (lane == 0) ? __ldg(c0 + j) : 0.f;
    const float nl_scale = (lane == 2) ? 2.f : 1.f;   // tanh lane via sig(2x)

    for (int t = 0; t < SEQ; t++) {
        // xg prefetch (independent of h): lanes 0..3 fetch this unit's gates
        float xr = 0.f;
        if (lane < 4)
            xr = __ldg(g_xg + (size_t)t * FH + lane * HID + j);

        if (t > 0) {
            if (tid < NB) {
                const unsigned int* f = &g_flag[tid * 8];
                while (ld_acq(f) < (unsigned int)t) { }
            }
            __syncthreads();
        }
        const float* hsrc = (t == 0) ? h0 : g_hbuf[(t - 1) & 1];

        // Cooperative coalesced h load: 256 threads x float4 = 1024 floats.
        {
            float4 hv = __ldcg((const float4*)hsrc + tid);
            int k = tid * 4;
            int col = tid >> 3;                 // (4*tid+e)>>5, e<4
            sh[(k + 0) & 31][col] = hv.x;
            sh[(k + 1) & 31][col] = hv.y;
            sh[(k + 2) & 31][col] = hv.z;
            sh[(k + 3) & 31][col] = hv.w;
        }
        __syncthreads();

        // Mat-vec: this thread covers k = lane*32 .. lane*32+31.
        // h[lane*32 + i] lives at sh[i][lane]  (conflict-free reads).
        unsigned long long a0 = pk2(0.f, 0.f), a1 = a0, a2 = a0, a3 = a0;
#pragma unroll
        for (int q = 0; q < 16; q++) {
            unsigned long long h2 = pk2(sh[2 * q][lane], sh[2 * q + 1][lane]);
            a0 = fma2(w2[0][q], h2, a0);
            a1 = fma2(w2[1][q], h2, a1);
            a2 = fma2(w2[2][q], h2, a2);
            a3 = fma2(w2[3][q], h2, a3);
        }
        float acc[4];
        { float x, y; upk2(a0, x, y); acc[0] = x + y;
          upk2(a1, x, y); acc[1] = x + y;
          upk2(a2, x, y); acc[2] = x + y;
          upk2(a3, x, y); acc[3] = x + y; }
#pragma unroll
        for (int off = 16; off >= 1; off >>= 1) {
            acc[0] += __shfl_xor_sync(0xffffffffu, acc[0], off);
            acc[1] += __shfl_xor_sync(0xffffffffu, acc[1], off);
            acc[2] += __shfl_xor_sync(0xffffffffu, acc[2], off);
            acc[3] += __shfl_xor_sync(0xffffffffu, acc[3], off);
        }

        // lanes 0..3 compute the four gate activations in parallel
        float act = 0.f;
        if (lane < 4) {
            float p = acc[lane] + xr;
            float s = 1.f / (1.f + __expf(-nl_scale * p));
            act = (lane == 2) ? (2.f * s - 1.f) : s;
        }
        float iv = __shfl_sync(0xffffffffu, act, 0);
        float fv = __shfl_sync(0xffffffffu, act, 1);
        float gv = __shfl_sync(0xffffffffu, act, 2);
        float ov = __shfl_sync(0xffffffffu, act, 3);
        if (lane == 0) {
            cst = fv * cst + iv * gv;
            float s2 = 1.f / (1.f + __expf(-2.f * cst));
            g_hbuf[t & 1][j] = ov * (2.f * s2 - 1.f);
        }
        __syncthreads();   // all units' h stores done (cta scope)
        if (tid == 0)
            st_rel(&g_flag[blockIdx.x * 8], (unsigned int)(t + 1));
    }
}

// ---------------------------------------------------------------------------
// Kernel C: reset flags so the captured graph replays deterministically.
// ---------------------------------------------------------------------------
__global__ void reset_flags_k() {
    g_flag[threadIdx.x] = 0u;
}

// ---------------------------------------------------------------------------
// Kernel D: out = log_softmax(h_final)
// ---------------------------------------------------------------------------
__global__ __launch_bounds__(1024) void logsoftmax_k(float* __restrict__ out)
{
    __shared__ float red[32];
    __shared__ float s_m, s_s;
    const int tid = threadIdx.x;
    float x = g_hbuf[(SEQ - 1) & 1][tid];

    float m = x;
#pragma unroll
    for (int off = 16; off >= 1; off >>= 1)
        m = fmaxf(m, __shfl_xor_sync(0xffffffffu, m, off));
    if ((tid & 31) == 0) red[tid >> 5] = m;
    __syncthreads();
    if (tid < 32) {
        float v = red[tid];
#pragma unroll
        for (int off = 16; off >= 1; off >>= 1)
            v = fmaxf(v, __shfl_xor_sync(0xffffffffu, v, off));
        if (tid == 0) s_m = v;
    }
    __syncthreads();

    float e = __expf(x - s_m);
    float s = e;
#pragma unroll
    for (int off = 16; off >= 1; off >>= 1)
        s += __shfl_xor_sync(0xffffffffu, s, off);
    if ((tid & 31) == 0) red[tid >> 5] = s;
    __syncthreads();
    if (tid < 32) {
        float v = red[tid];
#pragma unroll
        for (int off = 16; off >= 1; off >>= 1)
            v += __shfl_xor_sync(0xffffffffu, v, off);
        if (tid == 0) s_s = v;
    }
    __syncthreads();

    out[tid] = x - s_m - logf(s_s);
}

// ---------------------------------------------------------------------------
extern "C" void kernel_launch(void* const* d_in, const int* in_sizes, int n_in,
                              void* d_out, int out_size)
{
    const int*   tok = (const int*)  d_in[0];
    const float* emb = (const float*)d_in[1];
    const float* Wih = (const float*)d_in[2];
    const float* Whh = (const float*)d_in[3];
    const float* bih = (const float*)d_in[4];
    const float* bhh = (const float*)d_in[5];
    const float* h0  = (const float*)d_in[6];
    const float* c0  = (const float*)d_in[7];
    float* out = (float*)d_out;

    xg_gemm<<<dim3(FH / 128, SEQ / 128), 256>>>(tok, emb, Wih, bih, bhh);
    lstm_scan<<<NB, 256>>>(Whh, h0, c0);
    reset_flags_k<<<1, NB * 8>>>();
    logsoftmax_k<<<1, 1024>>>(out);
}